// round 2
// baseline (speedup 1.0000x reference)
#include <cuda_runtime.h>
#include <math.h>

#define B_ 4
#define N_ 1024
#define M_ 1024
#define D_ 512
#define EPS_ 0.1f
#define INV_EPS 10.0f
#define THRESH_ 0.1f
#define MAX_ITER_ 20

// Scratch (device globals — no allocation allowed)
__device__ float g_C [(size_t)B_ * N_ * M_];   // C[b,i,j], 16 MB
__device__ float g_Ct[(size_t)B_ * N_ * M_];   // C[b,j,i], 16 MB
__device__ float g_nx[B_ * N_];
__device__ float g_ny[B_ * M_];
__device__ float g_u [B_ * N_];
__device__ float g_v [B_ * M_];
__device__ float g_err[MAX_ITER_];
__device__ int   g_done;

// ---------------------------------------------------------------------------
// init: zero state each launch (graph replays must be deterministic)
// ---------------------------------------------------------------------------
__global__ void k_init(float* out) {
    int t = blockIdx.x * blockDim.x + threadIdx.x;
    if (t < B_ * N_) g_u[t] = 0.0f;
    if (t < B_ * M_) g_v[t] = 0.0f;
    if (t < MAX_ITER_) g_err[t] = 0.0f;
    if (t < B_) out[t] = 0.0f;
    if (t == 0) g_done = 0;
}

// ---------------------------------------------------------------------------
// norms: one warp per row (x rows then y rows)
// ---------------------------------------------------------------------------
__global__ void k_norms(const float* __restrict__ X, const float* __restrict__ Y) {
    int gwarp = (blockIdx.x * blockDim.x + threadIdx.x) >> 5;
    int lane = threadIdx.x & 31;
    const float* base;
    float* outp;
    if (gwarp < B_ * N_) {
        base = X + (size_t)gwarp * D_;
        outp = g_nx + gwarp;
    } else {
        int r = gwarp - B_ * N_;
        base = Y + (size_t)r * D_;
        outp = g_ny + r;
    }
    const float4* b4 = (const float4*)base;
    float s = 0.0f;
#pragma unroll
    for (int k = 0; k < 4; k++) {
        float4 v = b4[k * 32 + lane];
        s += v.x * v.x + v.y * v.y + v.z * v.z + v.w * v.w;
    }
#pragma unroll
    for (int o = 16; o; o >>= 1) s += __shfl_xor_sync(0xffffffffu, s, o);
    if (lane == 0) *outp = sqrtf(s);
}

// ---------------------------------------------------------------------------
// GEMM: C[b,i,j] = 1 - dot(x_i,y_j)/max(nx*ny, 1e-8); also writes C^T.
// 64x64 tile, K-step 16, 256 threads, each thread 4x4 micro-tile.
// ---------------------------------------------------------------------------
__global__ void k_gemm(const float* __restrict__ X, const float* __restrict__ Y) {
    __shared__ float xs[16][72];
    __shared__ float ys[16][72];
    __shared__ float ts[64][68];   // transpose staging (row stride 272B, 16B-aligned)

    int b  = blockIdx.z;
    int i0 = blockIdx.y * 64;
    int j0 = blockIdx.x * 64;
    int tid  = threadIdx.x;
    int trow = tid >> 4;        // 0..15
    int tcol = tid & 15;        // 0..15
    int lr = tid >> 2;          // 0..63
    int lc = (tid & 3) << 2;    // 0,4,8,12

    const float* Xb = X + (size_t)b * N_ * D_;
    const float* Yb = Y + (size_t)b * M_ * D_;

    float acc[4][4];
#pragma unroll
    for (int q = 0; q < 4; q++)
#pragma unroll
        for (int r = 0; r < 4; r++) acc[q][r] = 0.0f;

    for (int k0 = 0; k0 < D_; k0 += 16) {
        float4 xv = *(const float4*)(Xb + (size_t)(i0 + lr) * D_ + k0 + lc);
        float4 yv = *(const float4*)(Yb + (size_t)(j0 + lr) * D_ + k0 + lc);
        __syncthreads();
        xs[lc + 0][lr] = xv.x; xs[lc + 1][lr] = xv.y;
        xs[lc + 2][lr] = xv.z; xs[lc + 3][lr] = xv.w;
        ys[lc + 0][lr] = yv.x; ys[lc + 1][lr] = yv.y;
        ys[lc + 2][lr] = yv.z; ys[lc + 3][lr] = yv.w;
        __syncthreads();
#pragma unroll
        for (int k = 0; k < 16; k++) {
            float xr[4], yr[4];
#pragma unroll
            for (int q = 0; q < 4; q++) { xr[q] = xs[k][trow * 4 + q]; yr[q] = ys[k][tcol * 4 + q]; }
#pragma unroll
            for (int q = 0; q < 4; q++)
#pragma unroll
                for (int r = 0; r < 4; r++) acc[q][r] += xr[q] * yr[r];
        }
    }

    // Epilogue: cost values, write C coalesced (float4), stage C^T via shared
    float* Crow = g_C + ((size_t)b * N_) * M_;
#pragma unroll
    for (int q = 0; q < 4; q++) {
        int i = i0 + trow * 4 + q;
        float nx = g_nx[b * N_ + i];
        float4 cv;
        float c[4];
#pragma unroll
        for (int r = 0; r < 4; r++) {
            int j = j0 + tcol * 4 + r;
            float denom = fmaxf(nx * g_ny[b * M_ + j], 1e-8f);
            c[r] = 1.0f - acc[q][r] / denom;
            ts[tcol * 4 + r][trow * 4 + q] = c[r];
        }
        cv.x = c[0]; cv.y = c[1]; cv.z = c[2]; cv.w = c[3];
        *(float4*)(Crow + (size_t)i * M_ + j0 + tcol * 4) = cv;
    }
    __syncthreads();
    // Coalesced transposed write: thread (lr, lc) covers i-chunks lc, lc+16, ...
    float* Ctb = g_Ct + ((size_t)b * M_) * N_ + (size_t)(j0 + lr) * N_ + i0;
#pragma unroll
    for (int c0 = 0; c0 < 64; c0 += 16) {
        int ii = c0 + lc;
        float4 v;
        v.x = ts[lr][ii + 0]; v.y = ts[lr][ii + 1];
        v.z = ts[lr][ii + 2]; v.w = ts[lr][ii + 3];
        *(float4*)(Ctb + ii) = v;
    }
}

// ---------------------------------------------------------------------------
// Row update: u_new_i = eps*(log_mu - lse_j((-C_ij + v_j)/eps))
// One warp per row; accumulates sum|du| into g_err[iter]; commits u in place.
// ---------------------------------------------------------------------------
__global__ void k_row(int iter) {
    if (g_done) return;
    __shared__ float sv[M_];
    int b = blockIdx.y;
    int tid = threadIdx.x;
    for (int t = tid; t < M_; t += 256) sv[t] = g_v[b * M_ + t];
    __syncthreads();

    int warp = tid >> 5, lane = tid & 31;
    int i = blockIdx.x * 8 + warp;
    const float4* crow = (const float4*)(g_C + ((size_t)b * N_ + i) * M_);

    float a[32];
    float mx = -3.402823466e38f;
#pragma unroll
    for (int k = 0; k < 8; k++) {
        int j4 = k * 32 + lane;
        float4 c = crow[j4];
        int j = j4 << 2;
        float a0 = (sv[j + 0] - c.x) * INV_EPS;
        float a1 = (sv[j + 1] - c.y) * INV_EPS;
        float a2 = (sv[j + 2] - c.z) * INV_EPS;
        float a3 = (sv[j + 3] - c.w) * INV_EPS;
        a[k * 4 + 0] = a0; a[k * 4 + 1] = a1; a[k * 4 + 2] = a2; a[k * 4 + 3] = a3;
        mx = fmaxf(mx, fmaxf(fmaxf(a0, a1), fmaxf(a2, a3)));
    }
#pragma unroll
    for (int o = 16; o; o >>= 1) mx = fmaxf(mx, __shfl_xor_sync(0xffffffffu, mx, o));
    float s = 0.0f;
#pragma unroll
    for (int k = 0; k < 32; k++) s += __expf(a[k] - mx);
#pragma unroll
    for (int o = 16; o; o >>= 1) s += __shfl_xor_sync(0xffffffffu, s, o);

    if (lane == 0) {
        float lse = mx + __logf(s);
        float log_mu = __logf(1.0f / (float)N_ + 1e-8f);
        float unew = EPS_ * (log_mu - lse);
        int idx = b * N_ + i;
        float d = fabsf(unew - g_u[idx]);
        g_u[idx] = unew;
        atomicAdd(&g_err[iter], d);
    }
}

// ---------------------------------------------------------------------------
// Col update: v_new_j = eps*(log_nu_j - lse_i((-C_ij + u_i)/eps)); uses C^T.
// ---------------------------------------------------------------------------
__global__ void k_col(const float* __restrict__ nu) {
    if (g_done) return;
    __shared__ float su[N_];
    int b = blockIdx.y;
    int tid = threadIdx.x;
    for (int t = tid; t < N_; t += 256) su[t] = g_u[b * N_ + t];
    __syncthreads();

    int warp = tid >> 5, lane = tid & 31;
    int j = blockIdx.x * 8 + warp;
    const float4* crow = (const float4*)(g_Ct + ((size_t)b * M_ + j) * N_);

    float a[32];
    float mx = -3.402823466e38f;
#pragma unroll
    for (int k = 0; k < 8; k++) {
        int i4 = k * 32 + lane;
        float4 c = crow[i4];
        int i = i4 << 2;
        float a0 = (su[i + 0] - c.x) * INV_EPS;
        float a1 = (su[i + 1] - c.y) * INV_EPS;
        float a2 = (su[i + 2] - c.z) * INV_EPS;
        float a3 = (su[i + 3] - c.w) * INV_EPS;
        a[k * 4 + 0] = a0; a[k * 4 + 1] = a1; a[k * 4 + 2] = a2; a[k * 4 + 3] = a3;
        mx = fmaxf(mx, fmaxf(fmaxf(a0, a1), fmaxf(a2, a3)));
    }
#pragma unroll
    for (int o = 16; o; o >>= 1) mx = fmaxf(mx, __shfl_xor_sync(0xffffffffu, mx, o));
    float s = 0.0f;
#pragma unroll
    for (int k = 0; k < 32; k++) s += __expf(a[k] - mx);
#pragma unroll
    for (int o = 16; o; o >>= 1) s += __shfl_xor_sync(0xffffffffu, s, o);

    if (lane == 0) {
        float lse = mx + __logf(s);
        float lnu = __logf(nu[b * M_ + j] + 1e-8f);
        g_v[b * M_ + j] = EPS_ * (lnu - lse);
    }
}

// ---------------------------------------------------------------------------
// Convergence check (matches reference ordering: commits this iter, then sets done)
// ---------------------------------------------------------------------------
__global__ void k_done(int iter) {
    if (!g_done && (g_err[iter] * (1.0f / (float)B_)) < THRESH_) g_done = 1;
}

// ---------------------------------------------------------------------------
// Final: cost[b] = sum_ij exp((-C + u_i + v_j)/eps) * C_ij
// ---------------------------------------------------------------------------
__global__ void k_cost(float* out) {
    __shared__ float sv[M_];
    int b = blockIdx.y;
    int tid = threadIdx.x;
    for (int t = tid; t < M_; t += 256) sv[t] = g_v[b * M_ + t];
    __syncthreads();

    int warp = tid >> 5, lane = tid & 31;
    int i = blockIdx.x * 8 + warp;
    float ui = g_u[b * N_ + i];
    const float4* crow = (const float4*)(g_C + ((size_t)b * N_ + i) * M_);

    float s = 0.0f;
#pragma unroll
    for (int k = 0; k < 8; k++) {
        int j4 = k * 32 + lane;
        float4 c = crow[j4];
        int j = j4 << 2;
        s += __expf((ui + sv[j + 0] - c.x) * INV_EPS) * c.x;
        s += __expf((ui + sv[j + 1] - c.y) * INV_EPS) * c.y;
        s += __expf((ui + sv[j + 2] - c.z) * INV_EPS) * c.z;
        s += __expf((ui + sv[j + 3] - c.w) * INV_EPS) * c.w;
    }
#pragma unroll
    for (int o = 16; o; o >>= 1) s += __shfl_xor_sync(0xffffffffu, s, o);
    if (lane == 0) atomicAdd(&out[b], s);
}

// ---------------------------------------------------------------------------
extern "C" void kernel_launch(void* const* d_in, const int* in_sizes, int n_in,
                              void* d_out, int out_size) {
    (void)in_sizes; (void)n_in; (void)out_size;
    const float* x  = (const float*)d_in[0];
    const float* y  = (const float*)d_in[1];
    const float* nu = (const float*)d_in[2];
    float* out = (float*)d_out;

    k_init<<<16, 256>>>(out);
    k_norms<<<1024, 256>>>(x, y);
    k_gemm<<<dim3(M_ / 64, N_ / 64, B_), 256>>>(x, y);
    for (int it = 0; it < MAX_ITER_; ++it) {
        k_row<<<dim3(N_ / 8, B_), 256>>>(it);
        k_col<<<dim3(M_ / 8, B_), 256>>>(nu);
        k_done<<<1, 1>>>(it);
    }
    k_cost<<<dim3(N_ / 8, B_), 256>>>(out);
}

// round 3
// speedup vs baseline: 1.3901x; 1.3901x over previous
#include <cuda_runtime.h>
#include <cuda_bf16.h>
#include <math.h>
#include <stdint.h>

#define B_ 4
#define N_ 1024
#define M_ 1024
#define D_ 512
#define EPS_ 0.1f
#define INV_EPS 10.0f
#define THRESH_ 0.1f
#define MAX_ITER_ 20
#define MU_CONST 0.0009765725f   /* 1/1024 + 1e-8 */
#define SAS 40                    /* smem row stride in bf16 for 32-wide k-chunk */

// ---------------- device scratch (no allocation allowed) ----------------
__device__ float g_C [(size_t)B_ * N_ * M_];   // cost matrix (for final cost)
__device__ float g_E [(size_t)B_ * N_ * M_];   // exp(-C/eps)
__device__ float g_Et[(size_t)B_ * N_ * M_];   // transposed E
__device__ __nv_bfloat16 g_xh[(size_t)B_ * N_ * D_];
__device__ __nv_bfloat16 g_xl[(size_t)B_ * N_ * D_];
__device__ __nv_bfloat16 g_yh[(size_t)B_ * M_ * D_];
__device__ __nv_bfloat16 g_yl[(size_t)B_ * M_ * D_];
__device__ float g_nx[B_ * N_];
__device__ float g_ny[B_ * M_];
__device__ float g_u [B_ * N_];   // u (for err metric only)
__device__ float g_eu[B_ * N_];   // exp(u/eps)
__device__ float g_ev[B_ * M_];   // exp(v/eps)
__device__ float g_err[MAX_ITER_];

// ---------------------------------------------------------------------------
__global__ void k_init(float* out) {
    int t = blockIdx.x * blockDim.x + threadIdx.x;
    if (t < B_ * N_) { g_u[t] = 0.0f; g_eu[t] = 1.0f; }
    if (t < B_ * M_) { g_ev[t] = 1.0f; }
    if (t < MAX_ITER_) g_err[t] = 0.0f;
    if (t < B_) out[t] = 0.0f;
}

// one warp per row (x rows then y rows)
__global__ void k_norms(const float* __restrict__ X, const float* __restrict__ Y) {
    int gwarp = (blockIdx.x * blockDim.x + threadIdx.x) >> 5;
    int lane = threadIdx.x & 31;
    const float* base;
    float* outp;
    if (gwarp < B_ * N_) {
        base = X + (size_t)gwarp * D_;
        outp = g_nx + gwarp;
    } else {
        int r = gwarp - B_ * N_;
        base = Y + (size_t)r * D_;
        outp = g_ny + r;
    }
    const float4* b4 = (const float4*)base;
    float s = 0.0f;
#pragma unroll
    for (int k = 0; k < 4; k++) {
        float4 v = b4[k * 32 + lane];
        s += v.x * v.x + v.y * v.y + v.z * v.z + v.w * v.w;
    }
#pragma unroll
    for (int o = 16; o; o >>= 1) s += __shfl_xor_sync(0xffffffffu, s, o);
    if (lane == 0) *outp = sqrtf(s);
}

// split-bf16 prep: v = hi + lo (hi,lo bf16); hi*hi products exact in fp32 MMA
__global__ void k_prep(const float* __restrict__ X, const float* __restrict__ Y) {
    int t = blockIdx.x * 256 + threadIdx.x;
    float v = X[t];
    __nv_bfloat16 h = __float2bfloat16(v);
    g_xh[t] = h;
    g_xl[t] = __float2bfloat16(v - __bfloat162float(h));
    float w = Y[t];
    __nv_bfloat16 g = __float2bfloat16(w);
    g_yh[t] = g;
    g_yl[t] = __float2bfloat16(w - __bfloat162float(g));
}

// ---------------------------------------------------------------------------
__device__ __forceinline__ void ldsm4(uint32_t& r0, uint32_t& r1, uint32_t& r2,
                                      uint32_t& r3, uint32_t addr) {
    asm volatile("ldmatrix.sync.aligned.m8n8.x4.shared.b16 {%0,%1,%2,%3},[%4];"
                 : "=r"(r0), "=r"(r1), "=r"(r2), "=r"(r3) : "r"(addr));
}
__device__ __forceinline__ void mma_bf16(float* d, const uint32_t* a,
                                         uint32_t b0, uint32_t b1) {
    asm volatile(
        "mma.sync.aligned.m16n8k16.row.col.f32.bf16.bf16.f32 "
        "{%0,%1,%2,%3},{%4,%5,%6,%7},{%8,%9},{%0,%1,%2,%3};"
        : "+f"(d[0]), "+f"(d[1]), "+f"(d[2]), "+f"(d[3])
        : "r"(a[0]), "r"(a[1]), "r"(a[2]), "r"(a[3]), "r"(b0), "r"(b1));
}

// 128x128 tile, 8 warps (2x4), warp tile 64x32, BK=32 bf16, 3 split passes.
// Epilogue: c = 1 - dot/max(nx*ny,1e-8); writes C, E=exp(-10c), Et.
__global__ __launch_bounds__(256, 2)
void k_gemm(int dummy) {
    __shared__ __align__(16) char smem_raw[40960];
    __nv_bfloat16* sAB = (__nv_bfloat16*)smem_raw;
    uint32_t sbase = (uint32_t)__cvta_generic_to_shared(smem_raw);

    int b = blockIdx.z;
    int i0 = blockIdx.y * 128;
    int j0 = blockIdx.x * 128;
    int tid = threadIdx.x;
    int lane = tid & 31, warp = tid >> 5;
    int wm = warp >> 2, wn = warp & 3;

    const __nv_bfloat16* Aps[3];
    const __nv_bfloat16* Bps[3];
    {
        size_t ao = (size_t)(b * N_ + i0) * D_;
        size_t bo = (size_t)(b * M_ + j0) * D_;
        Aps[0] = g_xh + ao; Bps[0] = g_yh + bo;
        Aps[1] = g_xh + ao; Bps[1] = g_yl + bo;
        Aps[2] = g_xl + ao; Bps[2] = g_yh + bo;
    }

    // loader mapping: 512 (row, chunk) pairs per matrix, 2 per thread
    int idx0 = tid, idx1 = tid + 256;
    int lr0 = idx0 >> 2, lc0 = (idx0 & 3) * 8;
    int lr1 = idx1 >> 2, lc1 = (idx1 & 3) * 8;

    // ldmatrix per-lane offsets
    int lr8 = lane & 7, seg = lane >> 3;
    int arow = (wm * 64 + lr8 + ((seg & 1) << 3)) * SAS + ((seg >> 1) << 3);
    int brow = (wn * 32 + lr8 + ((seg >> 1) << 3)) * SAS + ((seg & 1) << 3);

    float acc[4][4][4];
#pragma unroll
    for (int mi = 0; mi < 4; mi++)
#pragma unroll
        for (int nj = 0; nj < 4; nj++)
#pragma unroll
            for (int r = 0; r < 4; r++) acc[mi][nj][r] = 0.0f;

    float4 ra0, ra1, rb0, rb1;
    // preload stage 0
    ra0 = *(const float4*)(Aps[0] + lr0 * D_ + lc0);
    ra1 = *(const float4*)(Aps[0] + lr1 * D_ + lc1);
    rb0 = *(const float4*)(Bps[0] + lr0 * D_ + lc0);
    rb1 = *(const float4*)(Bps[0] + lr1 * D_ + lc1);
    *(float4*)&sAB[lr0 * SAS + lc0] = ra0;
    *(float4*)&sAB[lr1 * SAS + lc1] = ra1;
    *(float4*)&sAB[5120 + lr0 * SAS + lc0] = rb0;
    *(float4*)&sAB[5120 + lr1 * SAS + lc1] = rb1;
    __syncthreads();

    for (int s = 0; s < 48; s++) {
        int buf = s & 1;
        if (s + 1 < 48) {
            int p = (s + 1) >> 4;
            int kpos = ((s + 1) & 15) * 32;
            ra0 = *(const float4*)(Aps[p] + lr0 * D_ + kpos + lc0);
            ra1 = *(const float4*)(Aps[p] + lr1 * D_ + kpos + lc1);
            rb0 = *(const float4*)(Bps[p] + lr0 * D_ + kpos + lc0);
            rb1 = *(const float4*)(Bps[p] + lr1 * D_ + kpos + lc1);
        }
        uint32_t Ab = sbase + buf * 20480;
        uint32_t Bb = Ab + 10240;
#pragma unroll
        for (int kk = 0; kk < 32; kk += 16) {
            uint32_t a[4][4], br[2][4];
#pragma unroll
            for (int mi = 0; mi < 4; mi++)
                ldsm4(a[mi][0], a[mi][1], a[mi][2], a[mi][3],
                      Ab + (uint32_t)(arow + mi * 16 * SAS + kk) * 2);
#pragma unroll
            for (int nt = 0; nt < 2; nt++)
                ldsm4(br[nt][0], br[nt][1], br[nt][2], br[nt][3],
                      Bb + (uint32_t)(brow + nt * 16 * SAS + kk) * 2);
#pragma unroll
            for (int mi = 0; mi < 4; mi++)
#pragma unroll
                for (int nj = 0; nj < 4; nj++)
                    mma_bf16(acc[mi][nj], a[mi],
                             br[nj >> 1][(nj & 1) * 2], br[nj >> 1][(nj & 1) * 2 + 1]);
        }
        if (s + 1 < 48) {
            int nb = (s + 1) & 1;
            int e = nb * 10240;
            *(float4*)&sAB[e + lr0 * SAS + lc0] = ra0;
            *(float4*)&sAB[e + lr1 * SAS + lc1] = ra1;
            *(float4*)&sAB[e + 5120 + lr0 * SAS + lc0] = rb0;
            *(float4*)&sAB[e + 5120 + lr1 * SAS + lc1] = rb1;
        }
        __syncthreads();
    }

    // -------- epilogue: stage dot values half-tile at a time --------
    float* stg = (float*)smem_raw;   // 64 x (stride 132) floats = 33.8 KB
    const int ST = 132;
    size_t bN = (size_t)b * N_, bM = (size_t)b * M_;
    for (int h = 0; h < 2; h++) {
        __syncthreads();
        if (wm == h) {
#pragma unroll
            for (int mi = 0; mi < 4; mi++)
#pragma unroll
                for (int nj = 0; nj < 4; nj++) {
                    int rr = mi * 16 + (lane >> 2);
                    int cc = wn * 32 + nj * 8 + (lane & 3) * 2;
                    stg[rr * ST + cc]           = acc[mi][nj][0];
                    stg[rr * ST + cc + 1]       = acc[mi][nj][1];
                    stg[(rr + 8) * ST + cc]     = acc[mi][nj][2];
                    stg[(rr + 8) * ST + cc + 1] = acc[mi][nj][3];
                }
        }
        __syncthreads();
        // row-order outputs: C and E
#pragma unroll
        for (int q = 0; q < 8; q++) {
            int idx = tid + q * 256;
            int r = idx >> 5, cg = (idx & 31) * 4;
            int gi = i0 + h * 64 + r, gj = j0 + cg;
            float nxv = g_nx[bN + gi];
            float4 ny4 = *(const float4*)&g_ny[bM + gj];
            float4 dt = *(const float4*)&stg[r * ST + cg];
            float4 cv;
            cv.x = 1.0f - dt.x / fmaxf(nxv * ny4.x, 1e-8f);
            cv.y = 1.0f - dt.y / fmaxf(nxv * ny4.y, 1e-8f);
            cv.z = 1.0f - dt.z / fmaxf(nxv * ny4.z, 1e-8f);
            cv.w = 1.0f - dt.w / fmaxf(nxv * ny4.w, 1e-8f);
            size_t off = (bN + gi) * M_ + gj;
            *(float4*)&g_C[off] = cv;
            float4 e4;
            e4.x = __expf(-INV_EPS * cv.x);
            e4.y = __expf(-INV_EPS * cv.y);
            e4.z = __expf(-INV_EPS * cv.z);
            e4.w = __expf(-INV_EPS * cv.w);
            *(float4*)&g_E[off] = e4;
        }
        // transposed outputs: Et
#pragma unroll
        for (int q = 0; q < 8; q++) {
            int idx = tid + q * 256;
            int jr = idx >> 4, ig = (idx & 15) * 4;
            int gj = j0 + jr;
            int gi0 = i0 + h * 64 + ig;
            float nyv = g_ny[bM + gj];
            float4 nx4 = *(const float4*)&g_nx[bN + gi0];
            float d0 = stg[(ig + 0) * ST + jr];
            float d1 = stg[(ig + 1) * ST + jr];
            float d2 = stg[(ig + 2) * ST + jr];
            float d3 = stg[(ig + 3) * ST + jr];
            float4 e4;
            e4.x = __expf(-INV_EPS * (1.0f - d0 / fmaxf(nx4.x * nyv, 1e-8f)));
            e4.y = __expf(-INV_EPS * (1.0f - d1 / fmaxf(nx4.y * nyv, 1e-8f)));
            e4.z = __expf(-INV_EPS * (1.0f - d2 / fmaxf(nx4.z * nyv, 1e-8f)));
            e4.w = __expf(-INV_EPS * (1.0f - d3 / fmaxf(nx4.w * nyv, 1e-8f)));
            *(float4*)&g_Et[(bM + gj) * (size_t)N_ + gi0] = e4;
        }
    }
}

// ---------------------------------------------------------------------------
// sticky freeze flag: any earlier iteration with err < B*thresh
__device__ __forceinline__ int frozen(int it) {
    for (int t = 0; t < it; t++)
        if (g_err[t] < THRESH_ * (float)B_) return 1;
    return 0;
}

// row GEMV: r_i = sum_j E_ij * ev_j ; eu_i = mu / r_i ; accumulate err
__global__ void k_rowE(int iter) {
    __shared__ int sfroz;
    __shared__ __align__(16) float sev[M_];
    int tid = threadIdx.x;
    if (tid == 0) sfroz = frozen(iter);
    __syncthreads();
    if (sfroz) return;
    int b = blockIdx.y;
    for (int t = tid; t < M_; t += 256) sev[t] = g_ev[b * M_ + t];
    __syncthreads();

    int warp = tid >> 5, lane = tid & 31;
    int i = blockIdx.x * 8 + warp;
    const float4* Er = (const float4*)(g_E + ((size_t)b * N_ + i) * M_);
    const float4* ev4 = (const float4*)sev;
    float s = 0.0f;
#pragma unroll
    for (int k = 0; k < 8; k++) {
        int j4 = k * 32 + lane;
        float4 e = Er[j4];
        float4 w = ev4[j4];
        s += e.x * w.x + e.y * w.y + e.z * w.z + e.w * w.w;
    }
#pragma unroll
    for (int o = 16; o; o >>= 1) s += __shfl_xor_sync(0xffffffffu, s, o);
    if (lane == 0) {
        int idx = b * N_ + i;
        float eu_new = MU_CONST / s;
        float unew = EPS_ * __logf(eu_new);
        float d = fabsf(unew - g_u[idx]);
        g_u[idx] = unew;
        g_eu[idx] = eu_new;
        atomicAdd(&g_err[iter], d);
    }
}

// col GEMV: c_j = sum_i Et_ji * eu_i ; ev_j = (nu_j + 1e-8) / c_j
__global__ void k_colE(const float* __restrict__ nu, int iter) {
    __shared__ int sfroz;
    __shared__ __align__(16) float seu[N_];
    int tid = threadIdx.x;
    if (tid == 0) sfroz = frozen(iter);
    __syncthreads();
    if (sfroz) return;
    int b = blockIdx.y;
    for (int t = tid; t < N_; t += 256) seu[t] = g_eu[b * N_ + t];
    __syncthreads();

    int warp = tid >> 5, lane = tid & 31;
    int j = blockIdx.x * 8 + warp;
    const float4* Er = (const float4*)(g_Et + ((size_t)b * M_ + j) * N_);
    const float4* eu4 = (const float4*)seu;
    float s = 0.0f;
#pragma unroll
    for (int k = 0; k < 8; k++) {
        int i4 = k * 32 + lane;
        float4 e = Er[i4];
        float4 w = eu4[i4];
        s += e.x * w.x + e.y * w.y + e.z * w.z + e.w * w.w;
    }
#pragma unroll
    for (int o = 16; o; o >>= 1) s += __shfl_xor_sync(0xffffffffu, s, o);
    if (lane == 0) {
        g_ev[b * M_ + j] = (nu[b * M_ + j] + 1e-8f) / s;
    }
}

// cost[b] = sum_ij eu_i * ev_j * E_ij * C_ij
__global__ void k_cost(float* out) {
    __shared__ __align__(16) float sev[M_];
    int b = blockIdx.y;
    int tid = threadIdx.x;
    for (int t = tid; t < M_; t += 256) sev[t] = g_ev[b * M_ + t];
    __syncthreads();

    int warp = tid >> 5, lane = tid & 31;
    int i = blockIdx.x * 8 + warp;
    size_t off = ((size_t)b * N_ + i) * M_;
    const float4* Er = (const float4*)(g_E + off);
    const float4* Cr = (const float4*)(g_C + off);
    const float4* ev4 = (const float4*)sev;
    float s = 0.0f;
#pragma unroll
    for (int k = 0; k < 8; k++) {
        int j4 = k * 32 + lane;
        float4 e = Er[j4];
        float4 c = Cr[j4];
        float4 w = ev4[j4];
        s += e.x * w.x * c.x + e.y * w.y * c.y + e.z * w.z * c.z + e.w * w.w * c.w;
    }
#pragma unroll
    for (int o = 16; o; o >>= 1) s += __shfl_xor_sync(0xffffffffu, s, o);
    if (lane == 0) atomicAdd(&out[b], g_eu[b * N_ + i] * s);
}

// ---------------------------------------------------------------------------
extern "C" void kernel_launch(void* const* d_in, const int* in_sizes, int n_in,
                              void* d_out, int out_size) {
    (void)in_sizes; (void)n_in; (void)out_size;
    const float* x  = (const float*)d_in[0];
    const float* y  = (const float*)d_in[1];
    const float* nu = (const float*)d_in[2];
    float* out = (float*)d_out;

    k_init<<<16, 256>>>(out);
    k_norms<<<1024, 256>>>(x, y);
    k_prep<<<8192, 256>>>(x, y);
    k_gemm<<<dim3(8, 8, B_), 256>>>(0);
    for (int it = 0; it < MAX_ITER_; ++it) {
        k_rowE<<<dim3(128, B_), 256>>>(it);
        k_colE<<<dim3(128, B_), 256>>>(nu, it);
    }
    k_cost<<<dim3(128, B_), 256>>>(out);
}

// round 9
// speedup vs baseline: 1.7644x; 1.2692x over previous
#include <cuda_runtime.h>
#include <cuda_bf16.h>
#include <math.h>
#include <stdint.h>

#define B_ 4
#define N_ 1024
#define M_ 1024
#define D_ 512
#define EPS_ 0.1f
#define INV_EPS 10.0f
#define THRESH_ 0.1f
#define MAX_ITER_ 20
#define MU_CONST 0.0009765725f   /* 1/1024 + 1e-8 */
#define SAS 24                    /* smem row stride (bf16) for 16-wide k-chunk */

// ---------------- device scratch (no allocation allowed) ----------------
__device__ float g_C [(size_t)B_ * N_ * M_];          // cost matrix fp32 (for final cost)
__device__ __nv_bfloat16 g_E [(size_t)B_ * N_ * M_];  // exp(-C/eps) bf16
__device__ __nv_bfloat16 g_Et[(size_t)B_ * N_ * M_];  // transposed E bf16
__device__ __nv_bfloat16 g_xh[(size_t)B_ * N_ * D_];
__device__ __nv_bfloat16 g_xl[(size_t)B_ * N_ * D_];
__device__ __nv_bfloat16 g_yh[(size_t)B_ * M_ * D_];
__device__ float g_nx[B_ * N_];
__device__ float g_ny[B_ * M_];
__device__ float g_u [B_ * N_];   // u (for err metric)
__device__ float g_eu[B_ * N_];   // exp(u/eps)
__device__ float g_ev[B_ * M_];   // exp(v/eps)
__device__ float g_err[MAX_ITER_];

__device__ __forceinline__ uint32_t pack_bf2(float a, float b) {
    __nv_bfloat162 t = __floats2bfloat162_rn(a, b);
    return *(uint32_t*)&t;
}
__device__ __forceinline__ float2 b2f(uint32_t u) {
    __nv_bfloat162 h = *reinterpret_cast<__nv_bfloat162*>(&u);
    return __bfloat1622float2(h);
}

// ---------------------------------------------------------------------------
// fused: state init + norms + bf16 split prep. 1024 blocks x 8 warps = 8192 rows.
// ---------------------------------------------------------------------------
__global__ void k_prep(const float* __restrict__ X, const float* __restrict__ Y,
                       float* out) {
    int tid = threadIdx.x;
    if (blockIdx.x == 0) {
        for (int t = tid; t < B_ * N_; t += 256) { g_u[t] = 0.0f; g_eu[t] = 1.0f; }
        for (int t = tid; t < B_ * M_; t += 256) g_ev[t] = 1.0f;
        if (tid < MAX_ITER_) g_err[tid] = 0.0f;
        if (tid < B_) out[tid] = 0.0f;
    }
    int warp = tid >> 5, lane = tid & 31;
    int r = blockIdx.x * 8 + warp;          // 0..8191
    bool isx = r < B_ * N_;
    int rr = isx ? r : r - B_ * N_;
    const float4* s4 = (const float4*)((isx ? X : Y) + (size_t)rr * D_);
    float ss = 0.0f;
#pragma unroll
    for (int k = 0; k < 4; k++) {
        int idx = k * 32 + lane;            // float4 index within row (0..127)
        float4 v = s4[idx];
        ss += v.x * v.x + v.y * v.y + v.z * v.z + v.w * v.w;
        __nv_bfloat16 hx = __float2bfloat16(v.x);
        __nv_bfloat16 hy = __float2bfloat16(v.y);
        __nv_bfloat16 hz = __float2bfloat16(v.z);
        __nv_bfloat16 hw = __float2bfloat16(v.w);
        uint2 hi;
        { __nv_bfloat162 t; t.x = hx; t.y = hy; hi.x = *(uint32_t*)&t; }
        { __nv_bfloat162 t; t.x = hz; t.y = hw; hi.y = *(uint32_t*)&t; }
        size_t e = (size_t)rr * D_ + idx * 4;
        if (isx) {
            *(uint2*)&g_xh[e] = hi;
            uint2 lo;
            lo.x = pack_bf2(v.x - __bfloat162float(hx), v.y - __bfloat162float(hy));
            lo.y = pack_bf2(v.z - __bfloat162float(hz), v.w - __bfloat162float(hw));
            *(uint2*)&g_xl[e] = lo;
        } else {
            *(uint2*)&g_yh[e] = hi;
        }
    }
#pragma unroll
    for (int o = 16; o; o >>= 1) ss += __shfl_xor_sync(0xffffffffu, ss, o);
    if (lane == 0) {
        if (isx) g_nx[rr] = sqrtf(ss);
        else     g_ny[rr] = sqrtf(ss);
    }
}

// ---------------------------------------------------------------------------
__device__ __forceinline__ void ldsm4(uint32_t& r0, uint32_t& r1, uint32_t& r2,
                                      uint32_t& r3, uint32_t addr) {
    asm volatile("ldmatrix.sync.aligned.m8n8.x4.shared.b16 {%0,%1,%2,%3},[%4];"
                 : "=r"(r0), "=r"(r1), "=r"(r2), "=r"(r3) : "r"(addr));
}
__device__ __forceinline__ void mma_bf16(float* d, const uint32_t* a,
                                         uint32_t b0, uint32_t b1) {
    asm volatile(
        "mma.sync.aligned.m16n8k16.row.col.f32.bf16.bf16.f32 "
        "{%0,%1,%2,%3},{%4,%5,%6,%7},{%8,%9},{%0,%1,%2,%3};"
        : "+f"(d[0]), "+f"(d[1]), "+f"(d[2]), "+f"(d[3])
        : "r"(a[0]), "r"(a[1]), "r"(a[2]), "r"(a[3]), "r"(b0), "r"(b1));
}

// 128x128 tile, 8 warps (2x4), warp tile 64x32, BK=16, fused 2-pass split:
// acc += xh*yh + xl*yh, same B tile serves both A passes.
// Epilogue: c = 1 - dot/max(nx*ny,1e-8); writes C fp32, E bf16, Et bf16.
__global__ __launch_bounds__(256, 2)
void k_gemm() {
    __shared__ __align__(16) char smem_raw[36864];
    __nv_bfloat16* sAB = (__nv_bfloat16*)smem_raw;
    uint32_t sbase = (uint32_t)__cvta_generic_to_shared(smem_raw);

    int b = blockIdx.z;
    int i0 = blockIdx.y * 128;
    int j0 = blockIdx.x * 128;
    int tid = threadIdx.x;
    int lane = tid & 31, warp = tid >> 5;
    int wm = warp >> 2, wn = warp & 3;

    const __nv_bfloat16* Ah = g_xh + (size_t)(b * N_ + i0) * D_;
    const __nv_bfloat16* Al = g_xl + (size_t)(b * N_ + i0) * D_;
    const __nv_bfloat16* Bp = g_yh + (size_t)(b * M_ + j0) * D_;

    // loader: 128 rows x 2 chunks of 8 bf16 -> 256 (row,chunk) pairs, 1/thread/matrix
    int lr = tid >> 1;
    int lcH = (tid & 1) * 8;
    int sIdx = lr * SAS + lcH;

    // ldmatrix per-lane offsets (bf16 units)
    int lr8 = lane & 7, seg = lane >> 3;
    int arow = (wm * 64 + lr8 + ((seg & 1) << 3)) * SAS + ((seg >> 1) << 3);
    int brow = (wn * 32 + lr8 + ((seg >> 1) << 3)) * SAS + ((seg & 1) << 3);

    float acc[4][4][4];
#pragma unroll
    for (int mi = 0; mi < 4; mi++)
#pragma unroll
        for (int nj = 0; nj < 4; nj++)
#pragma unroll
            for (int r = 0; r < 4; r++) acc[mi][nj][r] = 0.0f;

    const int STG = 9216;    // stage stride in bf16 ELEMENTS (18432 B)
    const int MATB = 3072;   // per-matrix stride in bf16 elements (6144 B)

    float4 fa, fl, fb;
    fa = *(const float4*)(Ah + lr * D_ + lcH);
    fl = *(const float4*)(Al + lr * D_ + lcH);
    fb = *(const float4*)(Bp + lr * D_ + lcH);
    *(float4*)&sAB[sIdx]            = fa;
    *(float4*)&sAB[MATB + sIdx]     = fl;
    *(float4*)&sAB[2 * MATB + sIdx] = fb;
    __syncthreads();

    for (int s = 0; s < 32; s++) {
        int buf = s & 1;
        if (s + 1 < 32) {
            int k0 = (s + 1) * 16;
            fa = *(const float4*)(Ah + lr * D_ + k0 + lcH);
            fl = *(const float4*)(Al + lr * D_ + k0 + lcH);
            fb = *(const float4*)(Bp + lr * D_ + k0 + lcH);
        }
        uint32_t Sb = sbase + buf * (STG * 2);   // byte address of stage
        uint32_t Bb = Sb + 2 * MATB * 2;
        uint32_t bfr[2][4];
#pragma unroll
        for (int nt = 0; nt < 2; nt++)
            ldsm4(bfr[nt][0], bfr[nt][1], bfr[nt][2], bfr[nt][3],
                  Bb + (uint32_t)(brow + nt * 16 * SAS) * 2);
        {
            uint32_t a[4][4];
#pragma unroll
            for (int mi = 0; mi < 4; mi++)
                ldsm4(a[mi][0], a[mi][1], a[mi][2], a[mi][3],
                      Sb + (uint32_t)(arow + mi * 16 * SAS) * 2);
#pragma unroll
            for (int mi = 0; mi < 4; mi++)
#pragma unroll
                for (int nj = 0; nj < 4; nj++)
                    mma_bf16(acc[mi][nj], a[mi],
                             bfr[nj >> 1][(nj & 1) * 2], bfr[nj >> 1][(nj & 1) * 2 + 1]);
#pragma unroll
            for (int mi = 0; mi < 4; mi++)
                ldsm4(a[mi][0], a[mi][1], a[mi][2], a[mi][3],
                      Sb + MATB * 2 + (uint32_t)(arow + mi * 16 * SAS) * 2);
#pragma unroll
            for (int mi = 0; mi < 4; mi++)
#pragma unroll
                for (int nj = 0; nj < 4; nj++)
                    mma_bf16(acc[mi][nj], a[mi],
                             bfr[nj >> 1][(nj & 1) * 2], bfr[nj >> 1][(nj & 1) * 2 + 1]);
        }
        if (s + 1 < 32) {
            int e = ((s + 1) & 1) * STG;   // ELEMENT offset (bug fix: was *2)
            *(float4*)&sAB[e + sIdx]            = fa;
            *(float4*)&sAB[e + MATB + sIdx]     = fl;
            *(float4*)&sAB[e + 2 * MATB + sIdx] = fb;
        }
        __syncthreads();
    }

    // -------- epilogue: stage dot values half-tile at a time --------
    float* stg = (float*)smem_raw;   // 64 x (stride 132) floats = 33.8 KB (fits)
    const int ST = 132;
    size_t bN = (size_t)b * N_, bM = (size_t)b * M_;
    for (int h = 0; h < 2; h++) {
        __syncthreads();
        if (wm == h) {
#pragma unroll
            for (int mi = 0; mi < 4; mi++)
#pragma unroll
                for (int nj = 0; nj < 4; nj++) {
                    int rr = mi * 16 + (lane >> 2);
                    int cc = wn * 32 + nj * 8 + (lane & 3) * 2;
                    stg[rr * ST + cc]           = acc[mi][nj][0];
                    stg[rr * ST + cc + 1]       = acc[mi][nj][1];
                    stg[(rr + 8) * ST + cc]     = acc[mi][nj][2];
                    stg[(rr + 8) * ST + cc + 1] = acc[mi][nj][3];
                }
        }
        __syncthreads();
        // row-order outputs: C fp32, E bf16
#pragma unroll
        for (int q = 0; q < 8; q++) {
            int idx = tid + q * 256;
            int r = idx >> 5, cg = (idx & 31) * 4;
            int gi = i0 + h * 64 + r, gj = j0 + cg;
            float nxv = g_nx[bN + gi];
            float4 ny4 = *(const float4*)&g_ny[bM + gj];
            float4 dt = *(const float4*)&stg[r * ST + cg];
            float4 cv;
            cv.x = 1.0f - dt.x / fmaxf(nxv * ny4.x, 1e-8f);
            cv.y = 1.0f - dt.y / fmaxf(nxv * ny4.y, 1e-8f);
            cv.z = 1.0f - dt.z / fmaxf(nxv * ny4.z, 1e-8f);
            cv.w = 1.0f - dt.w / fmaxf(nxv * ny4.w, 1e-8f);
            size_t off = (bN + gi) * M_ + gj;
            *(float4*)&g_C[off] = cv;
            uint2 e2;
            e2.x = pack_bf2(__expf(-INV_EPS * cv.x), __expf(-INV_EPS * cv.y));
            e2.y = pack_bf2(__expf(-INV_EPS * cv.z), __expf(-INV_EPS * cv.w));
            *(uint2*)&g_E[off] = e2;
        }
        // transposed outputs: Et bf16
#pragma unroll
        for (int q = 0; q < 8; q++) {
            int idx = tid + q * 256;
            int jr = idx >> 4, ig = (idx & 15) * 4;
            int gj = j0 + jr;
            int gi0 = i0 + h * 64 + ig;
            float nyv = g_ny[bM + gj];
            float4 nx4 = *(const float4*)&g_nx[bN + gi0];
            float d0 = stg[(ig + 0) * ST + jr];
            float d1 = stg[(ig + 1) * ST + jr];
            float d2 = stg[(ig + 2) * ST + jr];
            float d3 = stg[(ig + 3) * ST + jr];
            float e0 = __expf(-INV_EPS * (1.0f - d0 / fmaxf(nx4.x * nyv, 1e-8f)));
            float e1 = __expf(-INV_EPS * (1.0f - d1 / fmaxf(nx4.y * nyv, 1e-8f)));
            float e2v = __expf(-INV_EPS * (1.0f - d2 / fmaxf(nx4.z * nyv, 1e-8f)));
            float e3 = __expf(-INV_EPS * (1.0f - d3 / fmaxf(nx4.w * nyv, 1e-8f)));
            uint2 p;
            p.x = pack_bf2(e0, e1);
            p.y = pack_bf2(e2v, e3);
            *(uint2*)&g_Et[(bM + gj) * (size_t)N_ + gi0] = p;
        }
    }
}

// ---------------------------------------------------------------------------
// sticky freeze flag: any earlier iteration with err < B*thresh
__device__ __forceinline__ int frozen(int it) {
    for (int t = 0; t < it; t++)
        if (g_err[t] < THRESH_ * (float)B_) return 1;
    return 0;
}

// row GEMV: r_i = sum_j E_ij * ev_j ; eu_i = mu / r_i ; accumulate err
// grid (64, B), 16 rows/block (2 per warp)
__global__ void k_rowE(int iter) {
    __shared__ int sfz;
    __shared__ float serrv;
    __shared__ __align__(16) float sev[M_];
    int tid = threadIdx.x;
    if (tid == 0) { sfz = frozen(iter); serrv = 0.0f; }
    __syncthreads();
    if (sfz) return;
    int b = blockIdx.y;
    {
        float4* d4 = (float4*)sev;
        const float4* s4 = (const float4*)&g_ev[b * M_];
        d4[tid] = s4[tid];
    }
    __syncthreads();

    int warp = tid >> 5, lane = tid & 31;
    const float4* ev4 = (const float4*)sev;
    float dloc = 0.0f;
#pragma unroll
    for (int ri = 0; ri < 2; ri++) {
        int i = blockIdx.x * 16 + ri * 8 + warp;
        const uint4* Er = (const uint4*)(g_E + ((size_t)(b * N_ + i)) * M_);
        float s = 0.0f;
#pragma unroll
        for (int k = 0; k < 4; k++) {
            int c = k * 32 + lane;
            uint4 q = Er[c];
            float4 w0 = ev4[c * 2];
            float4 w1 = ev4[c * 2 + 1];
            float2 a0 = b2f(q.x), a1 = b2f(q.y), a2 = b2f(q.z), a3 = b2f(q.w);
            s += a0.x * w0.x + a0.y * w0.y + a1.x * w0.z + a1.y * w0.w;
            s += a2.x * w1.x + a2.y * w1.y + a3.x * w1.z + a3.y * w1.w;
        }
#pragma unroll
        for (int o = 16; o; o >>= 1) s += __shfl_xor_sync(0xffffffffu, s, o);
        if (lane == 0) {
            int idx = b * N_ + i;
            float eu_new = MU_CONST / s;
            float unew = EPS_ * __logf(eu_new);
            dloc += fabsf(unew - g_u[idx]);
            g_u[idx] = unew;
            g_eu[idx] = eu_new;
        }
    }
    if (lane == 0) atomicAdd(&serrv, dloc);
    __syncthreads();
    if (tid == 0) atomicAdd(&g_err[iter], serrv);
}

// col GEMV: c_j = sum_i Et_ji * eu_i ; ev_j = (nu_j + 1e-8) / c_j
__global__ void k_colE(const float* __restrict__ nu, int iter) {
    __shared__ int sfz;
    __shared__ __align__(16) float seu[N_];
    int tid = threadIdx.x;
    if (tid == 0) sfz = frozen(iter);
    __syncthreads();
    if (sfz) return;
    int b = blockIdx.y;
    {
        float4* d4 = (float4*)seu;
        const float4* s4 = (const float4*)&g_eu[b * N_];
        d4[tid] = s4[tid];
    }
    __syncthreads();

    int warp = tid >> 5, lane = tid & 31;
    const float4* eu4 = (const float4*)seu;
#pragma unroll
    for (int ri = 0; ri < 2; ri++) {
        int j = blockIdx.x * 16 + ri * 8 + warp;
        const uint4* Er = (const uint4*)(g_Et + ((size_t)(b * M_ + j)) * N_);
        float s = 0.0f;
#pragma unroll
        for (int k = 0; k < 4; k++) {
            int c = k * 32 + lane;
            uint4 q = Er[c];
            float4 w0 = eu4[c * 2];
            float4 w1 = eu4[c * 2 + 1];
            float2 a0 = b2f(q.x), a1 = b2f(q.y), a2 = b2f(q.z), a3 = b2f(q.w);
            s += a0.x * w0.x + a0.y * w0.y + a1.x * w0.z + a1.y * w0.w;
            s += a2.x * w1.x + a2.y * w1.y + a3.x * w1.z + a3.y * w1.w;
        }
#pragma unroll
        for (int o = 16; o; o >>= 1) s += __shfl_xor_sync(0xffffffffu, s, o);
        if (lane == 0)
            g_ev[b * M_ + j] = (nu[b * M_ + j] + 1e-8f) / s;
    }
}

// cost[b] = sum_ij eu_i * ev_j * exp(-C/eps) * C_ij   (C fp32)
__global__ void k_cost(float* out) {
    __shared__ __align__(16) float sev[M_];
    int b = blockIdx.y;
    int tid = threadIdx.x;
    {
        float4* d4 = (float4*)sev;
        const float4* s4 = (const float4*)&g_ev[b * M_];
        d4[tid] = s4[tid];
    }
    __syncthreads();

    int warp = tid >> 5, lane = tid & 31;
    int i = blockIdx.x * 8 + warp;
    size_t off = ((size_t)b * N_ + i) * M_;
    const float4* Cr = (const float4*)(g_C + off);
    const float4* ev4 = (const float4*)sev;
    float s = 0.0f;
#pragma unroll
    for (int k = 0; k < 8; k++) {
        int j4 = k * 32 + lane;
        float4 c = Cr[j4];
        float4 w = ev4[j4];
        s += __expf(-INV_EPS * c.x) * w.x * c.x;
        s += __expf(-INV_EPS * c.y) * w.y * c.y;
        s += __expf(-INV_EPS * c.z) * w.z * c.z;
        s += __expf(-INV_EPS * c.w) * w.w * c.w;
    }
#pragma unroll
    for (int o = 16; o; o >>= 1) s += __shfl_xor_sync(0xffffffffu, s, o);
    if (lane == 0) atomicAdd(&out[b], g_eu[b * N_ + i] * s);
}

// ---------------------------------------------------------------------------
extern "C" void kernel_launch(void* const* d_in, const int* in_sizes, int n_in,
                              void* d_out, int out_size) {
    (void)in_sizes; (void)n_in; (void)out_size;
    const float* x  = (const float*)d_in[0];
    const float* y  = (const float*)d_in[1];
    const float* nu = (const float*)d_in[2];
    float* out = (float*)d_out;

    k_prep<<<1024, 256>>>(x, y, out);
    k_gemm<<<dim3(8, 8, B_), 256>>>();
    for (int it = 0; it < MAX_ITER_; ++it) {
        k_rowE<<<dim3(64, B_), 256>>>(it);
        k_colE<<<dim3(64, B_), 256>>>(nu, it);
    }
    k_cost<<<dim3(128, B_), 256>>>(out);
}